// round 1
// baseline (speedup 1.0000x reference)
#include <cuda_runtime.h>
#include <math.h>

#define BATCH 4096
#define DIM   2048

// ---- scratch (static __device__ arrays: allocation-guard-safe) ----
__device__ float gLi[(size_t)BATCH * DIM];      // 32 MB  log_softmax(c_i)
__device__ float gQ [(size_t)BATCH * DIM];      // 32 MB  softmax(c_j)
__device__ float gH [BATCH];                    // hneg[j] = sum_k Q*logQ
__device__ float gCross[(size_t)BATCH * BATCH]; // 64 MB  Li @ Q^T
__device__ float gRowLoss[BATCH];

// ---------------- reductions (256-thread blocks, 8 warps) ----------------
__device__ __forceinline__ float warpMax(float v) {
    #pragma unroll
    for (int o = 16; o; o >>= 1) v = fmaxf(v, __shfl_xor_sync(0xffffffffu, v, o));
    return v;
}
__device__ __forceinline__ float warpSum(float v) {
    #pragma unroll
    for (int o = 16; o; o >>= 1) v += __shfl_xor_sync(0xffffffffu, v, o);
    return v;
}
// s must be a __shared__ float[8] buffer. Leading __syncthreads protects reuse.
__device__ __forceinline__ float blockMax256(float v, float* s) {
    v = warpMax(v);
    int w = threadIdx.x >> 5, l = threadIdx.x & 31;
    __syncthreads();
    if (l == 0) s[w] = v;
    __syncthreads();
    float r = s[0];
    #pragma unroll
    for (int i = 1; i < 8; ++i) r = fmaxf(r, s[i]);
    return r;
}
__device__ __forceinline__ float blockSum256(float v, float* s) {
    v = warpSum(v);
    int w = threadIdx.x >> 5, l = threadIdx.x & 31;
    __syncthreads();
    if (l == 0) s[w] = v;
    __syncthreads();
    float r = s[0];
    #pragma unroll
    for (int i = 1; i < 8; ++i) r += s[i];
    return r;
}

// ---------------- phase 1: row prep ----------------
// blocks [0, BATCH)        : c_i row -> gLi
// blocks [BATCH, 2*BATCH)  : c_j row -> gQ, gH
__global__ void rowprep_kernel(const float* __restrict__ ci,
                               const float* __restrict__ cj) {
    __shared__ float sred[8];
    const int blk  = blockIdx.x;
    const bool isJ = blk >= BATCH;
    const int row  = isJ ? blk - BATCH : blk;
    const float* src = (isJ ? cj : ci) + (size_t)row * DIM;
    const int tid = threadIdx.x;

    // 2048 floats / 256 threads = 8 per thread (2 float4)
    const float4* s4 = (const float4*)src;
    float4 v0 = s4[tid];
    float4 v1 = s4[tid + 256];
    float x[8] = {v0.x, v0.y, v0.z, v0.w, v1.x, v1.y, v1.z, v1.w};

    float m = x[0];
    #pragma unroll
    for (int i = 1; i < 8; ++i) m = fmaxf(m, x[i]);
    m = blockMax256(m, sred);

    float se = 0.f;
    #pragma unroll
    for (int i = 0; i < 8; ++i) se += expf(x[i] - m);
    se = blockSum256(se, sred);
    const float logZ = m + logf(se);

    if (!isJ) {
        float4 o0 = make_float4(x[0]-logZ, x[1]-logZ, x[2]-logZ, x[3]-logZ);
        float4 o1 = make_float4(x[4]-logZ, x[5]-logZ, x[6]-logZ, x[7]-logZ);
        float4* d4 = (float4*)(gLi + (size_t)row * DIM);
        d4[tid] = o0;
        d4[tid + 256] = o1;
    } else {
        float q[8], hn = 0.f;
        #pragma unroll
        for (int i = 0; i < 8; ++i) {
            float lq = x[i] - logZ;
            q[i] = expf(lq);
            hn += q[i] * lq;
        }
        float4 o0 = make_float4(q[0], q[1], q[2], q[3]);
        float4 o1 = make_float4(q[4], q[5], q[6], q[7]);
        float4* d4 = (float4*)(gQ + (size_t)row * DIM);
        d4[tid] = o0;
        d4[tid + 256] = o1;
        hn = blockSum256(hn, sred);
        if (tid == 0) gH[row] = hn;
    }
}

// ---------------- phase 2: cross = Li @ Q^T  (fp32 SIMT baseline) ----------------
// 128x128 block tile, BK=16, 256 threads, 8x8 per-thread microtile,
// register-prefetch to hide global latency.
#define BM 128
#define BN 128
#define BK 16
#define SPAD 4

__global__ __launch_bounds__(256, 2) void gemm_kernel() {
    __shared__ float As[BK][BM + SPAD];
    __shared__ float Bs[BK][BN + SPAD];

    const int tid = threadIdx.x;
    const int tx = tid & 15;   // j direction
    const int ty = tid >> 4;   // i direction
    const size_t rowBase = (size_t)blockIdx.y * BM;
    const size_t colBase = (size_t)blockIdx.x * BN;
    const float* A  = gLi + rowBase * DIM;
    const float* Bm = gQ  + colBase * DIM;

    // tile-load mapping: 128 rows x 16 k / float4 -> 512 f4, 2 per thread
    const int lr = tid >> 2;          // 0..63
    const int lc = (tid & 3) << 2;    // 0,4,8,12  (k within tile)

    float4 a0 = *(const float4*)(A  + (size_t)lr        * DIM + lc);
    float4 a1 = *(const float4*)(A  + (size_t)(lr + 64) * DIM + lc);
    float4 b0 = *(const float4*)(Bm + (size_t)lr        * DIM + lc);
    float4 b1 = *(const float4*)(Bm + (size_t)(lr + 64) * DIM + lc);

    float acc[8][8];
    #pragma unroll
    for (int i = 0; i < 8; ++i)
        #pragma unroll
        for (int j = 0; j < 8; ++j) acc[i][j] = 0.f;

    const int NT = DIM / BK;  // 128
    for (int kt = 0; kt < NT; ++kt) {
        // commit prefetched tile to smem (transposed: As[k][row])
        As[lc+0][lr]      = a0.x; As[lc+1][lr]      = a0.y;
        As[lc+2][lr]      = a0.z; As[lc+3][lr]      = a0.w;
        As[lc+0][lr+64]   = a1.x; As[lc+1][lr+64]   = a1.y;
        As[lc+2][lr+64]   = a1.z; As[lc+3][lr+64]   = a1.w;
        Bs[lc+0][lr]      = b0.x; Bs[lc+1][lr]      = b0.y;
        Bs[lc+2][lr]      = b0.z; Bs[lc+3][lr]      = b0.w;
        Bs[lc+0][lr+64]   = b1.x; Bs[lc+1][lr+64]   = b1.y;
        Bs[lc+2][lr+64]   = b1.z; Bs[lc+3][lr+64]   = b1.w;
        __syncthreads();

        if (kt + 1 < NT) {
            const int kn = (kt + 1) * BK;
            a0 = *(const float4*)(A  + (size_t)lr        * DIM + kn + lc);
            a1 = *(const float4*)(A  + (size_t)(lr + 64) * DIM + kn + lc);
            b0 = *(const float4*)(Bm + (size_t)lr        * DIM + kn + lc);
            b1 = *(const float4*)(Bm + (size_t)(lr + 64) * DIM + kn + lc);
        }

        #pragma unroll
        for (int k = 0; k < BK; ++k) {
            float4 af0 = *(const float4*)&As[k][ty * 8];
            float4 af1 = *(const float4*)&As[k][ty * 8 + 4];
            float4 bf0 = *(const float4*)&Bs[k][tx * 8];
            float4 bf1 = *(const float4*)&Bs[k][tx * 8 + 4];
            float a[8] = {af0.x, af0.y, af0.z, af0.w, af1.x, af1.y, af1.z, af1.w};
            float b[8] = {bf0.x, bf0.y, bf0.z, bf0.w, bf1.x, bf1.y, bf1.z, bf1.w};
            #pragma unroll
            for (int i = 0; i < 8; ++i)
                #pragma unroll
                for (int j = 0; j < 8; ++j)
                    acc[i][j] = fmaf(a[i], b[j], acc[i][j]);
        }
        __syncthreads();
    }

    #pragma unroll
    for (int i = 0; i < 8; ++i) {
        const size_t row = rowBase + (size_t)ty * 8 + i;
        float* dst = gCross + row * BATCH + colBase + tx * 8;
        *(float4*)(dst)     = make_float4(acc[i][0], acc[i][1], acc[i][2], acc[i][3]);
        *(float4*)(dst + 4) = make_float4(acc[i][4], acc[i][5], acc[i][6], acc[i][7]);
    }
}

// ---------------- phase 3: per-row logsumexp + diagonal ----------------
__global__ void rowlse_kernel() {
    __shared__ float sred[8];
    const int row = blockIdx.x;
    const float* cr = gCross + (size_t)row * BATCH;
    const int tid = threadIdx.x;

    float v[16];
    float m = -INFINITY;
    #pragma unroll
    for (int s = 0; s < 16; ++s) {
        const int j = tid + 256 * s;
        v[s] = 2.0f * (cr[j] - gH[j]);   // logits = -kl/T, T=0.5
        m = fmaxf(m, v[s]);
    }
    m = blockMax256(m, sred);

    float se = 0.f;
    #pragma unroll
    for (int s = 0; s < 16; ++s) se += expf(v[s] - m);
    se = blockSum256(se, sred);

    // the thread owning column j==row writes the per-row loss
    if (tid == (row & 255)) {
        const float lse  = m + logf(se);
        const float diag = v[row >> 8];
        gRowLoss[row] = lse - diag;
    }
}

// ---------------- phase 4: deterministic finalize ----------------
__global__ void finalize_kernel(float* __restrict__ out) {
    __shared__ float sred[8];
    float s = 0.f;
    for (int i = threadIdx.x; i < BATCH; i += 256) s += gRowLoss[i];
    s = blockSum256(s, sred);
    if (threadIdx.x == 0) out[0] = s / (float)BATCH;
}

// ---------------- launch ----------------
extern "C" void kernel_launch(void* const* d_in, const int* in_sizes, int n_in,
                              void* d_out, int out_size) {
    const float* ci = (const float*)d_in[0];
    const float* cj = (const float*)d_in[1];
    float* out = (float*)d_out;

    rowprep_kernel<<<2 * BATCH, 256>>>(ci, cj);
    dim3 grid(BATCH / BN, BATCH / BM);
    gemm_kernel<<<grid, 256>>>();
    rowlse_kernel<<<BATCH, 256>>>();
    finalize_kernel<<<1, 256>>>(out);
}

// round 3
// speedup vs baseline: 6.3679x; 6.3679x over previous
#include <cuda_runtime.h>
#include <cuda_bf16.h>
#include <math.h>
#include <stdint.h>

#define BATCH 4096
#define DIM   2048

// ---- scratch (static __device__ arrays: allocation-guard-safe) ----
__device__ __nv_bfloat16 gLib[(size_t)BATCH * DIM]; // 16 MB log_softmax(c_i) bf16
__device__ __nv_bfloat16 gQb [(size_t)BATCH * DIM]; // 16 MB softmax(c_j) bf16
__device__ float gH [BATCH];                        // hneg[j]
__device__ float gCross[(size_t)BATCH * BATCH];     // 64 MB Li @ Q^T (fp32)
__device__ float gRowLoss[BATCH];

// ===================== helpers =====================
__device__ __forceinline__ uint32_t smem_u32(const void* p) {
    uint32_t a;
    asm("{ .reg .u64 t; cvta.to.shared.u64 t, %1; cvt.u32.u64 %0, t; }" : "=r"(a) : "l"(p));
    return a;
}
__device__ __forceinline__ float warpMax(float v) {
    #pragma unroll
    for (int o = 16; o; o >>= 1) v = fmaxf(v, __shfl_xor_sync(0xffffffffu, v, o));
    return v;
}
__device__ __forceinline__ float warpSum(float v) {
    #pragma unroll
    for (int o = 16; o; o >>= 1) v += __shfl_xor_sync(0xffffffffu, v, o);
    return v;
}
__device__ __forceinline__ float blockMax256(float v, float* s) {
    v = warpMax(v);
    int w = threadIdx.x >> 5, l = threadIdx.x & 31;
    __syncthreads();
    if (l == 0) s[w] = v;
    __syncthreads();
    float r = s[0];
    #pragma unroll
    for (int i = 1; i < 8; ++i) r = fmaxf(r, s[i]);
    return r;
}
__device__ __forceinline__ float blockSum256(float v, float* s) {
    v = warpSum(v);
    int w = threadIdx.x >> 5, l = threadIdx.x & 31;
    __syncthreads();
    if (l == 0) s[w] = v;
    __syncthreads();
    float r = s[0];
    #pragma unroll
    for (int i = 1; i < 8; ++i) r += s[i];
    return r;
}

// ===================== phase 1: row prep (outputs bf16) =====================
__global__ void rowprep_kernel(const float* __restrict__ ci,
                               const float* __restrict__ cj) {
    __shared__ float sred[8];
    const int blk  = blockIdx.x;
    const bool isJ = blk >= BATCH;
    const int row  = isJ ? blk - BATCH : blk;
    const float* src = (isJ ? cj : ci) + (size_t)row * DIM;
    const int tid = threadIdx.x;

    const float4* s4 = (const float4*)src;
    float4 v0 = s4[tid];
    float4 v1 = s4[tid + 256];
    float x[8] = {v0.x, v0.y, v0.z, v0.w, v1.x, v1.y, v1.z, v1.w};

    float m = x[0];
    #pragma unroll
    for (int i = 1; i < 8; ++i) m = fmaxf(m, x[i]);
    m = blockMax256(m, sred);

    float se = 0.f;
    #pragma unroll
    for (int i = 0; i < 8; ++i) se += expf(x[i] - m);
    se = blockSum256(se, sred);
    const float logZ = m + logf(se);

    if (!isJ) {
        __nv_bfloat162* d2 = (__nv_bfloat162*)(gLib + (size_t)row * DIM);
        #pragma unroll
        for (int p = 0; p < 2; ++p)
            d2[tid * 2 + p] = __floats2bfloat162_rn(x[p*2] - logZ, x[p*2+1] - logZ);
        #pragma unroll
        for (int p = 0; p < 2; ++p)
            d2[512 + tid * 2 + p] = __floats2bfloat162_rn(x[4+p*2] - logZ, x[4+p*2+1] - logZ);
    } else {
        float q[8], hn = 0.f;
        #pragma unroll
        for (int i = 0; i < 8; ++i) {
            float lq = x[i] - logZ;
            q[i] = expf(lq);
            hn += q[i] * lq;
        }
        __nv_bfloat162* d2 = (__nv_bfloat162*)(gQb + (size_t)row * DIM);
        #pragma unroll
        for (int p = 0; p < 2; ++p)
            d2[tid * 2 + p] = __floats2bfloat162_rn(q[p*2], q[p*2+1]);
        #pragma unroll
        for (int p = 0; p < 2; ++p)
            d2[512 + tid * 2 + p] = __floats2bfloat162_rn(q[4+p*2], q[4+p*2+1]);
        hn = blockSum256(hn, sred);
        if (tid == 0) gH[row] = hn;
    }
}

// ===================== phase 2: bf16 mma.sync GEMM =====================
// cross = Li @ Q^T. CTA tile 128x128, warp tile 64x32 (2x4 warp grid),
// BK=32, 4-stage cp.async pipeline, ldmatrix fragments, fp32 accum.
#define BM 128
#define BN 128
#define BK 32
#define NS 4
#define ROWPITCH 80                       // 64B data + 16B pad: conflict-free ldmatrix
#define A_STAGE (BM * ROWPITCH)           // 10240
#define B_STAGE (BN * ROWPITCH)           // 10240
#define STAGE_BYTES (A_STAGE + B_STAGE)   // 20480
#define GEMM_SMEM (NS * STAGE_BYTES)      // 81920
#define NKT (DIM / BK)                    // 64

__device__ __forceinline__ void ldsm_x4(uint32_t& r0, uint32_t& r1, uint32_t& r2, uint32_t& r3,
                                        uint32_t addr) {
    asm volatile("ldmatrix.sync.aligned.m8n8.x4.shared.b16 {%0,%1,%2,%3}, [%4];"
                 : "=r"(r0), "=r"(r1), "=r"(r2), "=r"(r3) : "r"(addr));
}
__device__ __forceinline__ void mma16816(float* c, const uint32_t* a, uint32_t b0, uint32_t b1) {
    asm volatile(
        "mma.sync.aligned.m16n8k16.row.col.f32.bf16.bf16.f32 "
        "{%0,%1,%2,%3}, {%4,%5,%6,%7}, {%8,%9}, {%0,%1,%2,%3};"
        : "+f"(c[0]), "+f"(c[1]), "+f"(c[2]), "+f"(c[3])
        : "r"(a[0]), "r"(a[1]), "r"(a[2]), "r"(a[3]), "r"(b0), "r"(b1));
}

__device__ __forceinline__ void issue_stage(uint32_t stage_addr, int kt,
                                            size_t rowBase, size_t colBase, int tid) {
    const int kcol = kt * BK;
    // A: 128 rows x 4 chunks(16B) = 512 -> 2 per thread
    #pragma unroll
    for (int u = 0; u < 2; ++u) {
        int ch = tid + u * 256;
        int row = ch >> 2, sub = ch & 3;
        const __nv_bfloat16* src = gLib + (rowBase + row) * DIM + kcol + sub * 8;
        uint32_t dst = stage_addr + row * ROWPITCH + sub * 16;
        asm volatile("cp.async.cg.shared.global [%0], [%1], 16;" :: "r"(dst), "l"(src) : "memory");
    }
    // B: 128 rows x 4 chunks
    #pragma unroll
    for (int u = 0; u < 2; ++u) {
        int ch = tid + u * 256;
        int row = ch >> 2, sub = ch & 3;
        const __nv_bfloat16* src = gQb + (colBase + row) * DIM + kcol + sub * 8;
        uint32_t dst = stage_addr + A_STAGE + row * ROWPITCH + sub * 16;
        asm volatile("cp.async.cg.shared.global [%0], [%1], 16;" :: "r"(dst), "l"(src) : "memory");
    }
}

__global__ __launch_bounds__(256, 2) void gemm_mma_kernel() {
    extern __shared__ char smem[];
    const uint32_t sbase = smem_u32(smem);
    const int tid  = threadIdx.x;
    const int wid  = tid >> 5;
    const int lane = tid & 31;
    const int warpM = wid >> 2;        // 0..1  (64 rows each)
    const int warpN = wid & 3;         // 0..3  (32 cols each)
    const size_t rowBase = (size_t)blockIdx.y * BM;
    const size_t colBase = (size_t)blockIdx.x * BN;

    float c[4][4][4];
    #pragma unroll
    for (int m = 0; m < 4; ++m)
        #pragma unroll
        for (int n = 0; n < 4; ++n)
            #pragma unroll
            for (int r = 0; r < 4; ++r) c[m][n][r] = 0.f;

    // prologue: issue NS-1 stages
    #pragma unroll
    for (int s = 0; s < NS - 1; ++s) {
        issue_stage(sbase + s * STAGE_BYTES, s, rowBase, colBase, tid);
        asm volatile("cp.async.commit_group;" ::: "memory");
    }

    // per-lane ldmatrix address components (within-stage offsets)
    const int aRow = warpM * 64 + (lane & 15);
    const int aKby = (lane & 16) ? 16 : 0;
    const int bRow = warpN * 32 + (lane & 7) + ((lane & 16) ? 8 : 0);
    const int bKby = (lane & 8) ? 16 : 0;

    int s = 0;
    for (int kt = 0; kt < NKT; ++kt) {
        asm volatile("cp.async.wait_group %0;" :: "n"(NS - 2) : "memory");
        __syncthreads();

        const uint32_t aB = sbase + s * STAGE_BYTES;
        const uint32_t bB = aB + A_STAGE;

        #pragma unroll
        for (int ks = 0; ks < 2; ++ks) {
            uint32_t a[4][4], b[2][4];
            #pragma unroll
            for (int m = 0; m < 4; ++m)
                ldsm_x4(a[m][0], a[m][1], a[m][2], a[m][3],
                        aB + (aRow + m * 16) * ROWPITCH + ks * 32 + aKby);
            #pragma unroll
            for (int g = 0; g < 2; ++g)
                ldsm_x4(b[g][0], b[g][1], b[g][2], b[g][3],
                        bB + (bRow + g * 16) * ROWPITCH + ks * 32 + bKby);
            #pragma unroll
            for (int m = 0; m < 4; ++m)
                #pragma unroll
                for (int n = 0; n < 4; ++n)
                    mma16816(c[m][n], a[m], b[n >> 1][(n & 1) * 2], b[n >> 1][(n & 1) * 2 + 1]);
        }

        if (kt + NS - 1 < NKT)
            issue_stage(sbase + ((kt + NS - 1) % NS) * STAGE_BYTES, kt + NS - 1,
                        rowBase, colBase, tid);
        asm volatile("cp.async.commit_group;" ::: "memory");
        if (++s == NS) s = 0;
    }

    // epilogue: c[m][n] regs -> gCross. row0 = lane>>2, row1 = row0+8; col pair (lane&3)*2
    const int r0 = lane >> 2;
    const int cc = (lane & 3) * 2;
    #pragma unroll
    for (int m = 0; m < 4; ++m) {
        const size_t gr0 = rowBase + warpM * 64 + m * 16 + r0;
        float* d0 = gCross + gr0 * BATCH + colBase + warpN * 32 + cc;
        float* d1 = d0 + 8 * BATCH;
        #pragma unroll
        for (int n = 0; n < 4; ++n) {
            *(float2*)(d0 + n * 8) = make_float2(c[m][n][0], c[m][n][1]);
            *(float2*)(d1 + n * 8) = make_float2(c[m][n][2], c[m][n][3]);
        }
    }
}

// ===================== phase 3: per-row logsumexp + diagonal =====================
__global__ void rowlse_kernel() {
    __shared__ float sred[8];
    const int row = blockIdx.x;
    const float* cr = gCross + (size_t)row * BATCH;
    const int tid = threadIdx.x;

    float v[16];
    float m = -INFINITY;
    #pragma unroll
    for (int s = 0; s < 16; ++s) {
        const int j = tid + 256 * s;
        v[s] = 2.0f * (cr[j] - gH[j]);   // logits = -kl/T, T=0.5
        m = fmaxf(m, v[s]);
    }
    m = blockMax256(m, sred);

    float se = 0.f;
    #pragma unroll
    for (int s = 0; s < 16; ++s) se += expf(v[s] - m);
    se = blockSum256(se, sred);

    if (tid == (row & 255)) {
        const float lse  = m + logf(se);
        const float diag = v[row >> 8];
        gRowLoss[row] = lse - diag;
    }
}

// ===================== phase 4: finalize =====================
__global__ void finalize_kernel(float* __restrict__ out) {
    __shared__ float sred[8];
    float s = 0.f;
    for (int i = threadIdx.x; i < BATCH; i += 256) s += gRowLoss[i];
    s = blockSum256(s, sred);
    if (threadIdx.x == 0) out[0] = s / (float)BATCH;
}

// ===================== launch =====================
extern "C" void kernel_launch(void* const* d_in, const int* in_sizes, int n_in,
                              void* d_out, int out_size) {
    const float* ci = (const float*)d_in[0];
    const float* cj = (const float*)d_in[1];
    float* out = (float*)d_out;

    cudaFuncSetAttribute(gemm_mma_kernel, cudaFuncAttributeMaxDynamicSharedMemorySize, GEMM_SMEM);

    rowprep_kernel<<<2 * BATCH, 256>>>(ci, cj);
    dim3 grid(BATCH / BN, BATCH / BM);   // 32 x 32
    gemm_mma_kernel<<<grid, 256, GEMM_SMEM>>>();
    rowlse_kernel<<<BATCH, 256>>>();
    finalize_kernel<<<1, 256>>>(out);
}